// round 17
// baseline (speedup 1.0000x reference)
#include <cuda_runtime.h>

#define T_DIM 4096
#define D_DIM 64
#define B_DIM 32
#define BLK 128
#define TP   (T_DIM / 2)        // 2048 point-pairs per batch row (u64 units)
#define PM_REG 16               // pm[0..15] in registers, pm[16..62] in smem

typedef unsigned long long u64;   // two packed fp32 lanes (t, t+1)

__device__ __forceinline__ u64 fma2(u64 a, u64 b, u64 c) {
    u64 d; asm("fma.rn.f32x2 %0, %1, %2, %3;" : "=l"(d) : "l"(a), "l"(b), "l"(c)); return d;
}
__device__ __forceinline__ u64 mul2(u64 a, u64 b) {
    u64 d; asm("mul.rn.f32x2 %0, %1, %2;" : "=l"(d) : "l"(a), "l"(b)); return d;
}
__device__ __forceinline__ u64 add2(u64 a, u64 b) {
    u64 d; asm("add.rn.f32x2 %0, %1, %2;" : "=l"(d) : "l"(a), "l"(b)); return d;
}
#define HALF2 0x3F0000003F000000ULL   // {0.5f, 0.5f}

// pm accessor: registers for k < 16, private smem column otherwise.
// k is a compile-time constant after unrolling -> the ternary folds.
__device__ __forceinline__ u64 PM(int k, const u64* __restrict__ pmv,
                                  const u64* __restrict__ sp) {
    return (k < PM_REG) ? pmv[k] : sp[(k - PM_REG) * BLK];
}

// Deeper levels (M <= 16): R13 descending-p fused body, pm via accessor.
template<int M>
__device__ __forceinline__ void transition_d(const u64* __restrict__ F,
                                             u64* __restrict__ C,
                                             const u64* __restrict__ pmv,
                                             const u64* __restrict__ sp,
                                             const u64* __restrict__ dmb,
                                             int low, int up, u64& res)
{
    C[M - 1] = mul2(HALF2, add2(F[2 * M - 2], F[2 * M - 1]));

    u64 wbuf[4];
#pragma unroll
    for (int i = 0; i < (M < 4 ? M : 4); i++) {
        const int p = M - 1 - i;
        const int W = M + p;
        wbuf[p & 3] = (W >= low && W < up) ? dmb[(W - 1) * TP] : 0ULL;
    }

    u64 suf = 0ULL;
#pragma unroll
    for (int p = M - 1; p >= 1; p--) {
        const u64 w = wbuf[p & 3];
        if (p - 4 >= 0) {
            const int Wn = M + (p - 4);
            wbuf[(p - 4) & 3] = (Wn >= low && Wn < up) ? dmb[(Wn - 1) * TP] : 0ULL;
        }
        u64 sc = 0ULL;
#pragma unroll
        for (int j = p; j < M; j++) sc = fma2(C[j], PM(j + p, pmv, sp), sc);
        res = fma2(w, sc, res);
        suf = add2(suf, w);
        const u64 a = F[2 * p - 2], b = F[2 * p - 1];
        res = fma2(fma2(a, PM(2 * p - 2, pmv, sp), mul2(b, PM(2 * p - 1, pmv, sp))),
                   suf, res);
        C[p - 1] = mul2(HALF2, add2(a, b));
    }
    {   // p = 0: exact window W = M
        u64 sc = 0ULL;
#pragma unroll
        for (int j = 0; j < M; j++) sc = fma2(C[j], PM(j, pmv, sp), sc);
        res = fma2(wbuf[0], sc, res);
    }
}

// Level 0 (M = 32): k-descending form (validated in R3). Each pm[k] is read
// ONCE (k >= 16 from smem); C[j] born at k = 2j; w[p] lazily loaded 4
// iterations ahead (k = p + 35), dead after k = 2p -> small live sets.
__device__ __forceinline__ void level0(const u64* __restrict__ F,   // GMEM, stride TP
                                       u64* __restrict__ C,
                                       const u64* __restrict__ pmv,
                                       const u64* __restrict__ sp,
                                       const u64* __restrict__ dmb,
                                       int low, int up, u64& res)
{
    constexpr int M = 32;
    u64 w[M];
#pragma unroll
    for (int p = M - 1; p >= M - 4; p--) {            // prologue: p = 31..28
        const int W = M + p;
        w[p] = (W >= low && W < up) ? dmb[(W - 1) * TP] : 0ULL;
    }

    u64 fprev = F[(2 * M - 1) * TP];                  // F[63]
    u64 suf = 0ULL;
#pragma unroll
    for (int k = 2 * M - 2; k >= 0; k--) {            // k = 62 .. 0
        if (k >= 35) {                                // load w[k-35], 4 iters ahead of use
            const int p = k - 35;
            const int W = M + p;
            w[p] = (W >= low && W < up) ? dmb[(W - 1) * TP] : 0ULL;
        }
        if (k & 1) suf = add2(suf, w[(k + 1) / 2]);
        const u64 f = F[k * TP];
        if ((k & 1) == 0) C[k / 2] = mul2(HALF2, add2(f, fprev));
        fprev = f;

        u64 coef = (k <= 2 * M - 3) ? mul2(f, suf) : 0ULL;   // fine term
        const int pmin = (k - (M - 1) > 0) ? k - (M - 1) : 0;
        const int pmax = k / 2;
#pragma unroll
        for (int p = pmin; p <= pmax; p++)
            coef = fma2(w[p], C[k - p], coef);               // coarse correlation
        res = fma2(PM(k, pmv, sp), coef, res);
    }
}

__global__ __launch_bounds__(BLK, 4)   // 4 blocks/SM -> regs <= 128, single wave
void ContextGenerator_34875134444049_kernel(const float* __restrict__ rep_f,
                                            const float* __restrict__ dmask_f,
                                            const float* __restrict__ pmask_f,
                                            const int* __restrict__ lowp,
                                            const int* __restrict__ upp,
                                            float* __restrict__ out_f)
{
    // pm[16..62]: 47 rows x 128 u64 = 47 KB / block. Per-thread PRIVATE column
    // (only spm[... + tid] is ever touched by a thread) -> no __syncthreads.
    __shared__ u64 spm[(63 - PM_REG) * BLK];

    const int tid  = threadIdx.x;
    const int gid  = blockIdx.x * BLK + tid;          // pair id
    const int b    = gid >> 11;                       // TP = 2048
    const int tp   = gid & (TP - 1);
    const int base = b * (D_DIM * TP) + tp;           // u64 index

    const u64* __restrict__ rep = (const u64*)rep_f + base;
    const u64* __restrict__ dmb = (const u64*)dmask_f + base;
    const u64* __restrict__ pmb = (const u64*)pmask_f + base;

    const int low = *lowp;
    const int up  = *upp;

    // stage pm: 0..15 -> registers, 16..62 -> private smem column (batched LDGs)
    u64 pmv[PM_REG];
#pragma unroll
    for (int k = 0; k < PM_REG; k++) pmv[k] = pmb[k * TP];
#pragma unroll
    for (int k = PM_REG; k < 63; k++) spm[(k - PM_REG) * BLK + tid] = pmb[k * TP];

    const u64* __restrict__ sp = spm + tid;

    u64 res = 0ULL;

    u64 L1[32]; level0(rep, L1, pmv, sp, dmb, low, up, res);
    u64 L2[16]; transition_d<16>(L1, L2, pmv, sp, dmb, low, up, res);
    u64 L3[8];  transition_d<8>(L2, L3, pmv, sp, dmb, low, up, res);
    u64 L4[4];  transition_d<4>(L3, L4, pmv, sp, dmb, low, up, res);
    u64 L5[2];  transition_d<2>(L4, L5, pmv, sp, dmb, low, up, res);

    // W = 1: d = deepest level (single packed element)
    const u64 x6 = mul2(HALF2, add2(L5[0], L5[1]));
    if (1 >= low && 1 < up) res = fma2(dmb[0], mul2(x6, pmv[0]), res);

    ((u64*)out_f)[gid] = res;   // two adjacent t outputs
}

extern "C" void kernel_launch(void* const* d_in, const int* in_sizes, int n_in,
                              void* d_out, int out_size)
{
    const float* rep   = (const float*)d_in[0];
    const float* dmask = (const float*)d_in[1];
    const float* pmask = (const float*)d_in[2];
    const int*   lowp  = (const int*)d_in[3];
    const int*   upp   = (const int*)d_in[4];
    float* out = (float*)d_out;

    const int pairs = B_DIM * TP;              // 65536
    ContextGenerator_34875134444049_kernel<<<pairs / BLK, BLK>>>(
        rep, dmask, pmask, lowp, upp, out);
}